// round 16
// baseline (speedup 1.0000x reference)
#include <cuda_runtime.h>
#include <cuda_bf16.h>
#include <math.h>
#include <stdint.h>

#define NB 4
#define TSEQ 2048
#define DM 512
#define NH 8
#define HD 64
#define NTOK (NB * TSEQ)      // 8192
#define C3 (3 * DM)           // 1536
#define ATT_SCALE 0.125f

typedef __nv_bfloat16 bf16;

// Persistent scratch (no runtime allocation)
__device__ float g_qkv[NTOK * C3];
__device__ bf16  g_xh[NTOK * DM],   g_xl[NTOK * DM];
__device__ bf16  g_wqh[C3 * DM],    g_wql[C3 * DM];
__device__ bf16  g_owh[DM * DM],    g_owl[DM * DM];
__device__ bf16  g_qh[NTOK * DM],   g_ql[NTOK * DM];
__device__ bf16  g_kh[NTOK * DM],   g_kl[NTOK * DM];
__device__ bf16  g_vh[NTOK * DM],   g_vl[NTOK * DM];
__device__ bf16  g_ah[NTOK * DM],   g_al[NTOK * DM];

// ---------------------------------------------------------------------------
// helpers
// ---------------------------------------------------------------------------
__device__ __forceinline__ uint32_t smem_u32(const void* p) {
    uint32_t a;
    asm("{ .reg .u64 t; cvta.to.shared.u64 t, %1; cvt.u32.u64 %0, t; }"
        : "=r"(a) : "l"(p));
    return a;
}

#define LDSM_X4(r0, r1, r2, r3, addr)                                      \
    asm volatile("ldmatrix.sync.aligned.m8n8.x4.shared.b16 "               \
                 "{%0,%1,%2,%3}, [%4];"                                    \
                 : "=r"(r0), "=r"(r1), "=r"(r2), "=r"(r3) : "r"(addr))

#define LDSM_X4_T(r0, r1, r2, r3, addr)                                    \
    asm volatile("ldmatrix.sync.aligned.m8n8.x4.trans.shared.b16 "         \
                 "{%0,%1,%2,%3}, [%4];"                                    \
                 : "=r"(r0), "=r"(r1), "=r"(r2), "=r"(r3) : "r"(addr))

#define MMA_BF16(d, a, b)                                                  \
    asm volatile("mma.sync.aligned.m16n8k16.row.col.f32.bf16.bf16.f32 "    \
                 "{%0,%1,%2,%3}, {%4,%5,%6,%7}, {%8,%9}, {%0,%1,%2,%3};"   \
                 : "+f"((d)[0]), "+f"((d)[1]), "+f"((d)[2]), "+f"((d)[3])  \
                 : "r"((a)[0]), "r"((a)[1]), "r"((a)[2]), "r"((a)[3]),     \
                   "r"((b)[0]), "r"((b)[1]))

#define CP_ASYNC16(saddr, gptr)                                            \
    asm volatile("cp.async.cg.shared.global [%0], [%1], 16;"               \
                 :: "r"(saddr), "l"(gptr) : "memory")
#define CP_COMMIT() asm volatile("cp.async.commit_group;" ::: "memory")

__device__ __forceinline__ uint32_t pack_hi(float x, float y) {
    __nv_bfloat162 t;
    t.x = __float2bfloat16(x);
    t.y = __float2bfloat16(y);
    return *reinterpret_cast<uint32_t*>(&t);
}
__device__ __forceinline__ uint32_t pack_lo(float x, float y) {
    __nv_bfloat162 t;
    t.x = __float2bfloat16(x - __bfloat162float(__float2bfloat16(x)));
    t.y = __float2bfloat16(y - __bfloat162float(__float2bfloat16(y)));
    return *reinterpret_cast<uint32_t*>(&t);
}

// ---------------------------------------------------------------------------
// One-time fp32 -> bf16 hi/lo split
// ---------------------------------------------------------------------------
__global__ void split_f4(const float* __restrict__ src,
                         bf16* __restrict__ h, bf16* __restrict__ l, int n4)
{
    int i = blockIdx.x * blockDim.x + threadIdx.x;
    if (i >= n4) return;
    float4 a = ((const float4*)src)[i];
    ((uint2*)h)[i] = make_uint2(pack_hi(a.x, a.y), pack_hi(a.z, a.w));
    ((uint2*)l)[i] = make_uint2(pack_lo(a.x, a.y), pack_lo(a.z, a.w));
}

// ---------------------------------------------------------------------------
// bf16-plane HMMA GEMM: SW64 swizzle, 3-stage cp.async, 2 CTAs/SM.
// R14 change: stage(ch+2) issued BEFORE the MMA phase (overlaps compute).
// ---------------------------------------------------------------------------
#define KC 32
#define SWZ(x) ((uint32_t)(x) ^ ((((uint32_t)(x)) >> 3) & 0x30))
#define PLANE 8192
#define BUF   (4 * PLANE)
#define GEMM_SMEM (3 * BUF)

__global__ void __launch_bounds__(256, 2) gemm_bf(
    const bf16* __restrict__ Ah_, const bf16* __restrict__ Al_,
    const bf16* __restrict__ Bh_, const bf16* __restrict__ Bl_,
    float* __restrict__ C, const float* __restrict__ bias,
    int M, int N, int K)
{
    extern __shared__ char dsm[];
    const uint32_t sb = smem_u32(dsm);

    const int tid  = threadIdx.x;
    const int wid  = tid >> 5;
    const int lane = tid & 31;
    const int wm   = wid >> 2;
    const int wn   = wid & 3;
    const int mBase = blockIdx.y << 7;
    const int nBase = blockIdx.x << 7;

    const int srow = tid >> 2;
    const int sc   = tid & 3;
    const uint32_t sswz = SWZ(srow * 64 + sc * 16);
    const bf16* gAh = Ah_ + (size_t)(mBase + srow) * K + sc * 8;
    const bf16* gAl = Al_ + (size_t)(mBase + srow) * K + sc * 8;
    const bf16* gBh = Bh_ + (size_t)(nBase + srow) * K + sc * 8;
    const bf16* gBl = Bl_ + (size_t)(nBase + srow) * K + sc * 8;
    const size_t rs64 = (size_t)64 * K;

    const uint32_t aswz = SWZ((wm * 64 + (lane & 15)) * 64 + (lane >> 4) * 16);
    const uint32_t bswz = SWZ((wn * 32 + (lane & 15)) * 64 + (lane >> 4) * 16);

    float acc[4][4][4];
#pragma unroll
    for (int i = 0; i < 4; ++i)
#pragma unroll
        for (int j = 0; j < 4; ++j)
#pragma unroll
            for (int r = 0; r < 4; ++r) acc[i][j][r] = 0.f;

    const int nchunk = K / KC;

    auto stage = [&](int buf, int k0) {
        uint32_t base = sb + (uint32_t)(buf * BUF) + sswz;
        CP_ASYNC16(base,                    gAh + k0);
        CP_ASYNC16(base + 4096,             gAh + k0 + rs64);
        CP_ASYNC16(base + PLANE,            gAl + k0);
        CP_ASYNC16(base + PLANE + 4096,     gAl + k0 + rs64);
        CP_ASYNC16(base + 2 * PLANE,        gBh + k0);
        CP_ASYNC16(base + 2 * PLANE + 4096, gBh + k0 + rs64);
        CP_ASYNC16(base + 3 * PLANE,        gBl + k0);
        CP_ASYNC16(base + 3 * PLANE + 4096, gBl + k0 + rs64);
    };

    stage(0, 0);
    CP_COMMIT();
    if (nchunk > 1) { stage(1, KC); CP_COMMIT(); }

    int buf = 0;
    for (int ch = 0; ch < nchunk; ++ch) {
        if (ch + 1 < nchunk)
            asm volatile("cp.async.wait_group 1;" ::: "memory");
        else
            asm volatile("cp.async.wait_group 0;" ::: "memory");
        __syncthreads();   // all warps past iteration ch-1's reads

        // Issue prefetch of chunk ch+2 FIRST so the LDGSTS overlap the MMAs.
        // Target buffer (ch+2)%3 was last read in iteration ch-1, whose reads
        // the barrier above has already fenced.
        if (ch + 2 < nchunk) {
            stage((buf + 2) % 3, (ch + 2) * KC);
            CP_COMMIT();
        }

        const uint32_t bb = sb + (uint32_t)(buf * BUF);

#pragma unroll
        for (int ks = 0; ks < 2; ++ks) {
            const uint32_t kx = (uint32_t)(ks << 5);
            uint32_t ah[4][4], al[4][4], bh[4][2], bl[4][2];
#pragma unroll
            for (int mt = 0; mt < 4; ++mt) {
                uint32_t ad = (aswz ^ kx) + (uint32_t)(mt * 1024);
                LDSM_X4(ah[mt][0], ah[mt][1], ah[mt][2], ah[mt][3], bb + ad);
                LDSM_X4(al[mt][0], al[mt][1], al[mt][2], al[mt][3], bb + PLANE + ad);
            }
#pragma unroll
            for (int ntp = 0; ntp < 2; ++ntp) {
                uint32_t bd = (bswz ^ kx) + (uint32_t)(ntp * 1024);
                uint32_t r0, r1, r2, r3;
                LDSM_X4(r0, r1, r2, r3, bb + 2 * PLANE + bd);
                bh[2 * ntp][0] = r0; bh[2 * ntp][1] = r2;
                bh[2 * ntp + 1][0] = r1; bh[2 * ntp + 1][1] = r3;
                LDSM_X4(r0, r1, r2, r3, bb + 3 * PLANE + bd);
                bl[2 * ntp][0] = r0; bl[2 * ntp][1] = r2;
                bl[2 * ntp + 1][0] = r1; bl[2 * ntp + 1][1] = r3;
            }
#pragma unroll
            for (int mt = 0; mt < 4; ++mt)
#pragma unroll
                for (int nt = 0; nt < 4; ++nt)
                    MMA_BF16(acc[mt][nt], ah[mt], bh[nt]);
#pragma unroll
            for (int mt = 0; mt < 4; ++mt)
#pragma unroll
                for (int nt = 0; nt < 4; ++nt)
                    MMA_BF16(acc[mt][nt], ah[mt], bl[nt]);
#pragma unroll
            for (int mt = 0; mt < 4; ++mt)
#pragma unroll
                for (int nt = 0; nt < 4; ++nt)
                    MMA_BF16(acc[mt][nt], al[mt], bh[nt]);
        }

        buf = (buf + 1) % 3;
    }

    const int er = lane >> 2;
    const int ec = (lane & 3) << 1;
#pragma unroll
    for (int mt = 0; mt < 4; ++mt) {
#pragma unroll
        for (int nt = 0; nt < 4; ++nt) {
            int col = nBase + wn * 32 + nt * 8 + ec;
            float b0 = bias ? bias[col]     : 0.f;
            float b1 = bias ? bias[col + 1] : 0.f;
            int row0 = mBase + wm * 64 + mt * 16 + er;
            float2 v0 = make_float2(acc[mt][nt][0] + b0, acc[mt][nt][1] + b1);
            float2 v1 = make_float2(acc[mt][nt][2] + b0, acc[mt][nt][3] + b1);
            *(float2*)&C[(size_t)row0 * N + col]       = v0;
            *(float2*)&C[(size_t)(row0 + 8) * N + col] = v1;
        }
    }
}

// ---------------------------------------------------------------------------
// RoPE + split (vectorized, 1 double exp + float recurrence)
// ---------------------------------------------------------------------------
__global__ void rope_split(const float* __restrict__ qkv,
                           bf16* __restrict__ qh, bf16* __restrict__ ql,
                           bf16* __restrict__ kh, bf16* __restrict__ kl,
                           bf16* __restrict__ vh, bf16* __restrict__ vl)
{
    int idx = blockIdx.x * blockDim.x + threadIdx.x;
    if (idx >= NTOK * NH * 8) return;
    int j  = idx & 7;
    int h  = (idx >> 3) & (NH - 1);
    int nt = idx >> 6;
    int t  = nt & (TSEQ - 1);
    int i0 = j * 4;

    const float RSTEP = 0.74989420933245585f;   // 10000^(-1/32)
    float inv = (float)exp(-(double)i0 / 32.0 * 9.210340371976184);
    float s[4], c[4];
#pragma unroll
    for (int r = 0; r < 4; ++r) {
        sincosf((float)t * inv, &s[r], &c[r]);
        inv *= RSTEP;
    }

    const float* p = qkv + (size_t)nt * C3 + h * HD + i0;
    float4 qa = *(const float4*)p;
    float4 qb = *(const float4*)(p + 32);
    float4 ka = *(const float4*)(p + DM);
    float4 kb = *(const float4*)(p + DM + 32);
    float4 va = *(const float4*)(p + 2 * DM);
    float4 vb = *(const float4*)(p + 2 * DM + 32);

    float q1[4] = {qa.x, qa.y, qa.z, qa.w};
    float q2[4] = {qb.x, qb.y, qb.z, qb.w};
    float k1[4] = {ka.x, ka.y, ka.z, ka.w};
    float k2[4] = {kb.x, kb.y, kb.z, kb.w};
    float qr1[4], qr2[4], kr1[4], kr2[4];
#pragma unroll
    for (int r = 0; r < 4; ++r) {
        qr1[r] = q1[r] * c[r] - q2[r] * s[r];
        qr2[r] = q2[r] * c[r] + q1[r] * s[r];
        kr1[r] = k1[r] * c[r] - k2[r] * s[r];
        kr2[r] = k2[r] * c[r] + k1[r] * s[r];
    }

    size_t o = (size_t)nt * DM + h * HD + i0;
    *(uint2*)&qh[o]      = make_uint2(pack_hi(qr1[0], qr1[1]), pack_hi(qr1[2], qr1[3]));
    *(uint2*)&ql[o]      = make_uint2(pack_lo(qr1[0], qr1[1]), pack_lo(qr1[2], qr1[3]));
    *(uint2*)&qh[o + 32] = make_uint2(pack_hi(qr2[0], qr2[1]), pack_hi(qr2[2], qr2[3]));
    *(uint2*)&ql[o + 32] = make_uint2(pack_lo(qr2[0], qr2[1]), pack_lo(qr2[2], qr2[3]));
    *(uint2*)&kh[o]      = make_uint2(pack_hi(kr1[0], kr1[1]), pack_hi(kr1[2], kr1[3]));
    *(uint2*)&kl[o]      = make_uint2(pack_lo(kr1[0], kr1[1]), pack_lo(kr1[2], kr1[3]));
    *(uint2*)&kh[o + 32] = make_uint2(pack_hi(kr2[0], kr2[1]), pack_hi(kr2[2], kr2[3]));
    *(uint2*)&kl[o + 32] = make_uint2(pack_lo(kr2[0], kr2[1]), pack_lo(kr2[2], kr2[3]));
    *(uint2*)&vh[o]      = make_uint2(pack_hi(va.x, va.y), pack_hi(va.z, va.w));
    *(uint2*)&vl[o]      = make_uint2(pack_lo(va.x, va.y), pack_lo(va.z, va.w));
    *(uint2*)&vh[o + 32] = make_uint2(pack_hi(vb.x, vb.y), pack_hi(vb.z, vb.w));
    *(uint2*)&vl[o + 32] = make_uint2(pack_lo(vb.x, vb.y), pack_lo(vb.z, vb.w));
}

// ---------------------------------------------------------------------------
// HMMA banded flash attention (R11-exact: 128 threads, 64-query tile,
// static padded smem, native-V + trans ldmatrix, 4 CTAs/SM)
// ---------------------------------------------------------------------------
#define APAD  72
#define APADB 144

__global__ void __launch_bounds__(128) attn_bf(
    const bf16* __restrict__ qh_, const bf16* __restrict__ ql_,
    const bf16* __restrict__ kh_, const bf16* __restrict__ kl_,
    const bf16* __restrict__ vh_, const bf16* __restrict__ vl_,
    bf16* __restrict__ oh_, bf16* __restrict__ ol_)
{
    __shared__ bf16 Qh[64 * APAD], Ql[64 * APAD];
    __shared__ bf16 Kh[64 * APAD], Kl[64 * APAD];
    __shared__ bf16 Vh[64 * APAD], Vl[64 * APAD];

    const int tid  = threadIdx.x;
    const int wid  = tid >> 5;
    const int lane = tid & 31;
    const int qt = blockIdx.x, h = blockIdx.y, n = blockIdx.z;
    const int q0 = qt * 64;
    const size_t base = (size_t)n * TSEQ * DM + h * HD;

    const uint32_t baseQh = smem_u32(Qh), baseQl = smem_u32(Ql);
    const uint32_t baseKh = smem_u32(Kh), baseKl = smem_u32(Kl);
    const uint32_t baseVh = smem_u32(Vh), baseVl = smem_u32(Vl);

#pragma unroll
    for (int it = 0; it < 4; ++it) {
        int idx = it * 128 + tid;
        int row = idx >> 3;
        int f8  = (idx & 7) << 3;
        size_t g = base + (size_t)(q0 + row) * DM + f8;
        int so = row * APAD + f8;
        *(uint4*)&Qh[so] = *(const uint4*)&qh_[g];
        *(uint4*)&Ql[so] = *(const uint4*)&ql_[g];
    }
    __syncthreads();

    const uint32_t aOff = (uint32_t)((wid * 16 + (lane & 15)) * APADB
                                     + (lane >> 4) * 16);
    uint32_t qh[4][4], ql[4][4];
#pragma unroll
    for (int kt = 0; kt < 4; ++kt) {
        LDSM_X4(qh[kt][0], qh[kt][1], qh[kt][2], qh[kt][3], baseQh + aOff + kt * 32);
        LDSM_X4(ql[kt][0], ql[kt][1], ql[kt][2], ql[kt][3], baseQl + aOff + kt * 32);
    }

    float m_[2] = {-1e30f, -1e30f};
    float l_[2] = {0.f, 0.f};
    float oacc[8][4];
#pragma unroll
    for (int i = 0; i < 8; ++i)
#pragma unroll
        for (int r = 0; r < 4; ++r) oacc[i][r] = 0.f;

    const int kv_begin = max(0, q0 - 128);
    const int kv_end   = min(TSEQ, q0 + 64 + 128);

    const uint32_t bOff = (uint32_t)((lane & 15) * APADB + (lane >> 4) * 16);
    const int rbase = lane >> 2;
    const int cbase = (lane & 3) << 1;

    for (int kc = kv_begin; kc < kv_end; kc += 64) {
        __syncthreads();
#pragma unroll
        for (int it = 0; it < 4; ++it) {
            int idx = it * 128 + tid;
            int row = idx >> 3;
            int f8  = (idx & 7) << 3;
            size_t g = base + (size_t)(kc + row) * DM + f8;
            int so = row * APAD + f8;
            *(uint4*)&Kh[so] = *(const uint4*)&kh_[g];
            *(uint4*)&Kl[so] = *(const uint4*)&kl_[g];
            *(uint4*)&Vh[so] = *(const uint4*)&vh_[g];
            *(uint4*)&Vl[so] = *(const uint4*)&vl_[g];
        }
        __syncthreads();

        float sacc[8][4];
#pragma unroll
        for (int i = 0; i < 8; ++i)
#pragma unroll
            for (int r = 0; r < 4; ++r) sacc[i][r] = 0.f;

#pragma unroll
        for (int ntp = 0; ntp < 4; ++ntp) {
#pragma unroll
            for (int kt = 0; kt < 4; ++kt) {
                uint32_t ad = bOff + (uint32_t)(ntp * 16 * APADB) + (uint32_t)(kt * 32);
                uint32_t r0, r1, r2, r3, s0, s1, s2, s3;
                LDSM_X4(r0, r1, r2, r3, baseKh + ad);
                LDSM_X4(s0, s1, s2, s3, baseKl + ad);
                uint32_t bh0[2] = {r0, r2}, bh1[2] = {r1, r3};
                uint32_t bl0[2] = {s0, s2}, bl1[2] = {s1, s3};
                MMA_BF16(sacc[2 * ntp],     qh[kt], bh0);
                MMA_BF16(sacc[2 * ntp],     qh[kt], bl0);
                MMA_BF16(sacc[2 * ntp],     ql[kt], bh0);
                MMA_BF16(sacc[2 * ntp + 1], qh[kt], bh1);
                MMA_BF16(sacc[2 * ntp + 1], qh[kt], bl1);
                MMA_BF16(sacc[2 * ntp + 1], ql[kt], bh1);
            }
        }

        float mnew[2] = {m_[0], m_[1]};
#pragma unroll
        for (int nt = 0; nt < 8; ++nt) {
            int key0 = kc + nt * 8 + cbase;
#pragma unroll
            for (int half = 0; half < 2; ++half) {
                int q = q0 + wid * 16 + rbase + half * 8;
#pragma unroll
                for (int c = 0; c < 2; ++c) {
                    int diff = key0 + c - q;
                    bool vld = (diff >= -127) && (diff <= 128);
                    float sv = vld ? sacc[nt][half * 2 + c] * ATT_SCALE : -1e30f;
                    sacc[nt][half * 2 + c] = sv;
                    mnew[half] = fmaxf(mnew[half], sv);
                }
            }
        }
#pragma unroll
        for (int off = 1; off <= 2; off <<= 1) {
            mnew[0] = fmaxf(mnew[0], __shfl_xor_sync(0xffffffffu, mnew[0], off));
            mnew[1] = fmaxf(mnew[1], __shfl_xor_sync(0xffffffffu, mnew[1], off));
        }

        float sc0 = __expf(m_[0] - mnew[0]);
        float sc1 = __expf(m_[1] - mnew[1]);
        float ls[2] = {0.f, 0.f};

        uint32_t phi[4][4], plo[4][4];
#pragma unroll
        for (int kt = 0; kt < 4; ++kt) {
            int je = 2 * kt, jo = 2 * kt + 1;
            float p0 = __expf(sacc[je][0] - mnew[0]);
            float p1 = __expf(sacc[je][1] - mnew[0]);
            float p2 = __expf(sacc[je][2] - mnew[1]);
            float p3 = __expf(sacc[je][3] - mnew[1]);
            float p4 = __expf(sacc[jo][0] - mnew[0]);
            float p5 = __expf(sacc[jo][1] - mnew[0]);
            float p6 = __expf(sacc[jo][2] - mnew[1]);
            float p7 = __expf(sacc[jo][3] - mnew[1]);
            ls[0] += p0 + p1 + p4 + p5;
            ls[1] += p2 + p3 + p6 + p7;
            phi[kt][0] = pack_hi(p0, p1); plo[kt][0] = pack_lo(p0, p1);
            phi[kt][1] = pack_hi(p2, p3); plo[kt][1] = pack_lo(p2, p3);
            phi[kt][2] = pack_hi(p4, p5); plo[kt][2] = pack_lo(p4, p5);
            phi[kt][3] = pack_hi(p6, p7); plo[kt][3] = pack_lo(p6, p7);
        }
#pragma unroll
        for (int off = 1; off <= 2; off <<= 1) {
            ls[0] += __shfl_xor_sync(0xffffffffu, ls[0], off);
            ls[1] += __shfl_xor_sync(0xffffffffu, ls[1], off);
        }
        l_[0] = l_[0] * sc0 + ls[0];
        l_[1] = l_[1] * sc1 + ls[1];
        m_[0] = mnew[0];
        m_[1] = mnew[1];

#pragma unroll
        for (int nt = 0; nt < 8; ++nt) {
            oacc[nt][0] *= sc0; oacc[nt][1] *= sc0;
            oacc[nt][2] *= sc1; oacc[nt][3] *= sc1;
        }

#pragma unroll
        for (int ntp = 0; ntp < 4; ++ntp) {
#pragma unroll
            for (int kt = 0; kt < 4; ++kt) {
                uint32_t ad = bOff + (uint32_t)(kt * 16 * APADB) + (uint32_t)(ntp * 32);
                uint32_t r0, r1, r2, r3, s0, s1, s2, s3;
                LDSM_X4_T(r0, r1, r2, r3, baseVh + ad);
                LDSM_X4_T(s0, s1, s2, s3, baseVl + ad);
                uint32_t bh0[2] = {r0, r1}, bh1[2] = {r2, r3};
                uint32_t bl0[2] = {s0, s1}, bl1[2] = {s2, s3};
                MMA_BF16(oacc[2 * ntp],     phi[kt], bh0);
                MMA_BF16(oacc[2 * ntp],     phi[kt], bl0);
                MMA_BF16(oacc[2 * ntp],     plo[kt], bh0);
                MMA_BF16(oacc[2 * ntp + 1], phi[kt], bh1);
                MMA_BF16(oacc[2 * ntp + 1], phi[kt], bl1);
                MMA_BF16(oacc[2 * ntp + 1], plo[kt], bh1);
            }
        }
    }

    float inv0 = 1.f / l_[0];
    float inv1 = 1.f / l_[1];
    int q = q0 + wid * 16 + rbase;
#pragma unroll
    for (int nt = 0; nt < 8; ++nt) {
        int d = nt * 8 + cbase;
        size_t o0 = base + (size_t)q * DM + d;
        size_t o1 = base + (size_t)(q + 8) * DM + d;
        float a0 = oacc[nt][0] * inv0, a1 = oacc[nt][1] * inv0;
        float a2 = oacc[nt][2] * inv1, a3 = oacc[nt][3] * inv1;
        *(uint32_t*)&oh_[o0] = pack_hi(a0, a1);
        *(uint32_t*)&ol_[o0] = pack_lo(a0, a1);
        *(uint32_t*)&oh_[o1] = pack_hi(a2, a3);
        *(uint32_t*)&ol_[o1] = pack_lo(a2, a3);
    }
}

// ---------------------------------------------------------------------------
extern "C" void kernel_launch(void* const* d_in, const int* in_sizes, int n_in,
                              void* d_out, int out_size)
{
    const float* x    = (const float*)d_in[0];
    const float* wqkv = (const float*)d_in[1];
    const float* outw = (const float*)d_in[2];
    const float* outb = (const float*)d_in[3];
    float* out = (float*)d_out;

    void *qkvp, *xh, *xl, *wqh, *wql, *owh, *owl;
    void *qhp, *qlp, *khp, *klp, *vhp, *vlp, *ahp, *alp;
    cudaGetSymbolAddress(&qkvp, g_qkv);
    cudaGetSymbolAddress(&xh, g_xh);   cudaGetSymbolAddress(&xl, g_xl);
    cudaGetSymbolAddress(&wqh, g_wqh); cudaGetSymbolAddress(&wql, g_wql);
    cudaGetSymbolAddress(&owh, g_owh); cudaGetSymbolAddress(&owl, g_owl);
    cudaGetSymbolAddress(&qhp, g_qh);  cudaGetSymbolAddress(&qlp, g_ql);
    cudaGetSymbolAddress(&khp, g_kh);  cudaGetSymbolAddress(&klp, g_kl);
    cudaGetSymbolAddress(&vhp, g_vh);  cudaGetSymbolAddress(&vlp, g_vl);
    cudaGetSymbolAddress(&ahp, g_ah);  cudaGetSymbolAddress(&alp, g_al);

    cudaFuncSetAttribute(gemm_bf,
                         cudaFuncAttributeMaxDynamicSharedMemorySize, GEMM_SMEM);

    split_f4<<<(NTOK * DM / 4 + 255) / 256, 256>>>(x, (bf16*)xh, (bf16*)xl,
                                                   NTOK * DM / 4);
    split_f4<<<(C3 * DM / 4 + 255) / 256, 256>>>(wqkv, (bf16*)wqh, (bf16*)wql,
                                                 C3 * DM / 4);
    split_f4<<<(DM * DM / 4 + 255) / 256, 256>>>(outw, (bf16*)owh, (bf16*)owl,
                                                 DM * DM / 4);

    dim3 g1(C3 / 128, NTOK / 128);
    gemm_bf<<<g1, 256, GEMM_SMEM>>>((bf16*)xh, (bf16*)xl, (bf16*)wqh, (bf16*)wql,
                                    (float*)qkvp, nullptr, NTOK, C3, DM);

    int rt = NTOK * NH * 8;
    rope_split<<<(rt + 255) / 256, 256>>>((const float*)qkvp,
        (bf16*)qhp, (bf16*)qlp, (bf16*)khp, (bf16*)klp, (bf16*)vhp, (bf16*)vlp);

    dim3 g3(TSEQ / 64, NH, NB);
    attn_bf<<<g3, 128>>>((bf16*)qhp, (bf16*)qlp, (bf16*)khp, (bf16*)klp,
                         (bf16*)vhp, (bf16*)vlp, (bf16*)ahp, (bf16*)alp);

    dim3 g4(DM / 128, NTOK / 128);
    gemm_bf<<<g4, 256, GEMM_SMEM>>>((bf16*)ahp, (bf16*)alp, (bf16*)owh, (bf16*)owl,
                                    out, outb, NTOK, DM, DM);
}

// round 17
// speedup vs baseline: 1.6425x; 1.6425x over previous
#include <cuda_runtime.h>
#include <cuda_bf16.h>
#include <math.h>
#include <stdint.h>

#define NB 4
#define TSEQ 2048
#define DM 512
#define NH 8
#define HD 64
#define NTOK (NB * TSEQ)      // 8192
#define C3 (3 * DM)           // 1536
#define ATT_SCALE 0.125f

typedef __nv_bfloat16 bf16;

// Persistent scratch (no runtime allocation)
__device__ bf16  g_xh[NTOK * DM],   g_xl[NTOK * DM];
__device__ bf16  g_wqh[C3 * DM],    g_wql[C3 * DM];
__device__ bf16  g_owh[DM * DM],    g_owl[DM * DM];
__device__ bf16  g_qh[NTOK * DM],   g_ql[NTOK * DM];
__device__ bf16  g_kh[NTOK * DM],   g_kl[NTOK * DM];
__device__ bf16  g_vh[NTOK * DM],   g_vl[NTOK * DM];
__device__ bf16  g_ah[NTOK * DM],   g_al[NTOK * DM];

// ---------------------------------------------------------------------------
// helpers
// ---------------------------------------------------------------------------
__device__ __forceinline__ uint32_t smem_u32(const void* p) {
    uint32_t a;
    asm("{ .reg .u64 t; cvta.to.shared.u64 t, %1; cvt.u32.u64 %0, t; }"
        : "=r"(a) : "l"(p));
    return a;
}

#define LDSM_X4(r0, r1, r2, r3, addr)                                      \
    asm volatile("ldmatrix.sync.aligned.m8n8.x4.shared.b16 "               \
                 "{%0,%1,%2,%3}, [%4];"                                    \
                 : "=r"(r0), "=r"(r1), "=r"(r2), "=r"(r3) : "r"(addr))

#define LDSM_X4_T(r0, r1, r2, r3, addr)                                    \
    asm volatile("ldmatrix.sync.aligned.m8n8.x4.trans.shared.b16 "         \
                 "{%0,%1,%2,%3}, [%4];"                                    \
                 : "=r"(r0), "=r"(r1), "=r"(r2), "=r"(r3) : "r"(addr))

#define MMA_BF16(d, a, b)                                                  \
    asm volatile("mma.sync.aligned.m16n8k16.row.col.f32.bf16.bf16.f32 "    \
                 "{%0,%1,%2,%3}, {%4,%5,%6,%7}, {%8,%9}, {%0,%1,%2,%3};"   \
                 : "+f"((d)[0]), "+f"((d)[1]), "+f"((d)[2]), "+f"((d)[3])  \
                 : "r"((a)[0]), "r"((a)[1]), "r"((a)[2]), "r"((a)[3]),     \
                   "r"((b)[0]), "r"((b)[1]))

#define CP_ASYNC16(saddr, gptr)                                            \
    asm volatile("cp.async.cg.shared.global [%0], [%1], 16;"               \
                 :: "r"(saddr), "l"(gptr) : "memory")
#define CP_COMMIT() asm volatile("cp.async.commit_group;" ::: "memory")

__device__ __forceinline__ uint32_t pack_hi(float x, float y) {
    __nv_bfloat162 t;
    t.x = __float2bfloat16(x);
    t.y = __float2bfloat16(y);
    return *reinterpret_cast<uint32_t*>(&t);
}
__device__ __forceinline__ uint32_t pack_lo(float x, float y) {
    __nv_bfloat162 t;
    t.x = __float2bfloat16(x - __bfloat162float(__float2bfloat16(x)));
    t.y = __float2bfloat16(y - __bfloat162float(__float2bfloat16(y)));
    return *reinterpret_cast<uint32_t*>(&t);
}
__device__ __forceinline__ bf16 bhi(float x) { return __float2bfloat16(x); }
__device__ __forceinline__ bf16 blo(float x) {
    return __float2bfloat16(x - __bfloat162float(__float2bfloat16(x)));
}

// ---------------------------------------------------------------------------
// One-time fp32 -> bf16 hi/lo split
// ---------------------------------------------------------------------------
__global__ void split_f4(const float* __restrict__ src,
                         bf16* __restrict__ h, bf16* __restrict__ l, int n4)
{
    int i = blockIdx.x * blockDim.x + threadIdx.x;
    if (i >= n4) return;
    float4 a = ((const float4*)src)[i];
    ((uint2*)h)[i] = make_uint2(pack_hi(a.x, a.y), pack_hi(a.z, a.w));
    ((uint2*)l)[i] = make_uint2(pack_lo(a.x, a.y), pack_lo(a.z, a.w));
}

// ---------------------------------------------------------------------------
// Shared GEMM mainloop config (SW64 swizzle, 3-stage cp.async, 2 CTAs/SM)
// ---------------------------------------------------------------------------
#define KC 32
#define SWZ(x) ((uint32_t)(x) ^ ((((uint32_t)(x)) >> 3) & 0x30))
#define PLANE 8192
#define BUF   (4 * PLANE)
#define GEMM_SMEM (3 * BUF)

// Mainloop as a macro-like inline: declared inside each kernel to keep the
// measured R13 codegen. (Duplicated body; acc left in registers.)

// ---------------------------------------------------------------------------
// GEMM2: C[M,N] = A[M,K] B[N,K]^T + bias, fp32 out (R13-exact)
// ---------------------------------------------------------------------------
__global__ void __launch_bounds__(256, 2) gemm_bf(
    const bf16* __restrict__ Ah_, const bf16* __restrict__ Al_,
    const bf16* __restrict__ Bh_, const bf16* __restrict__ Bl_,
    float* __restrict__ C, const float* __restrict__ bias,
    int M, int N, int K)
{
    extern __shared__ char dsm[];
    const uint32_t sb = smem_u32(dsm);

    const int tid  = threadIdx.x;
    const int wid  = tid >> 5;
    const int lane = tid & 31;
    const int wm   = wid >> 2;
    const int wn   = wid & 3;
    const int mBase = blockIdx.y << 7;
    const int nBase = blockIdx.x << 7;

    const int srow = tid >> 2;
    const int sc   = tid & 3;
    const uint32_t sswz = SWZ(srow * 64 + sc * 16);
    const bf16* gAh = Ah_ + (size_t)(mBase + srow) * K + sc * 8;
    const bf16* gAl = Al_ + (size_t)(mBase + srow) * K + sc * 8;
    const bf16* gBh = Bh_ + (size_t)(nBase + srow) * K + sc * 8;
    const bf16* gBl = Bl_ + (size_t)(nBase + srow) * K + sc * 8;
    const size_t rs64 = (size_t)64 * K;

    const uint32_t aswz = SWZ((wm * 64 + (lane & 15)) * 64 + (lane >> 4) * 16);
    const uint32_t bswz = SWZ((wn * 32 + (lane & 15)) * 64 + (lane >> 4) * 16);

    float acc[4][4][4];
#pragma unroll
    for (int i = 0; i < 4; ++i)
#pragma unroll
        for (int j = 0; j < 4; ++j)
#pragma unroll
            for (int r = 0; r < 4; ++r) acc[i][j][r] = 0.f;

    const int nchunk = K / KC;

    auto stage = [&](int buf, int k0) {
        uint32_t base = sb + (uint32_t)(buf * BUF) + sswz;
        CP_ASYNC16(base,                    gAh + k0);
        CP_ASYNC16(base + 4096,             gAh + k0 + rs64);
        CP_ASYNC16(base + PLANE,            gAl + k0);
        CP_ASYNC16(base + PLANE + 4096,     gAl + k0 + rs64);
        CP_ASYNC16(base + 2 * PLANE,        gBh + k0);
        CP_ASYNC16(base + 2 * PLANE + 4096, gBh + k0 + rs64);
        CP_ASYNC16(base + 3 * PLANE,        gBl + k0);
        CP_ASYNC16(base + 3 * PLANE + 4096, gBl + k0 + rs64);
    };

    stage(0, 0);
    CP_COMMIT();
    if (nchunk > 1) { stage(1, KC); CP_COMMIT(); }

    int buf = 0;
    for (int ch = 0; ch < nchunk; ++ch) {
        if (ch + 1 < nchunk)
            asm volatile("cp.async.wait_group 1;" ::: "memory");
        else
            asm volatile("cp.async.wait_group 0;" ::: "memory");
        __syncthreads();

        const uint32_t bb = sb + (uint32_t)(buf * BUF);

#pragma unroll
        for (int ks = 0; ks < 2; ++ks) {
            const uint32_t kx = (uint32_t)(ks << 5);
            uint32_t ah[4][4], al[4][4], bh[4][2], bl[4][2];
#pragma unroll
            for (int mt = 0; mt < 4; ++mt) {
                uint32_t ad = (aswz ^ kx) + (uint32_t)(mt * 1024);
                LDSM_X4(ah[mt][0], ah[mt][1], ah[mt][2], ah[mt][3], bb + ad);
                LDSM_X4(al[mt][0], al[mt][1], al[mt][2], al[mt][3], bb + PLANE + ad);
            }
#pragma unroll
            for (int ntp = 0; ntp < 2; ++ntp) {
                uint32_t bd = (bswz ^ kx) + (uint32_t)(ntp * 1024);
                uint32_t r0, r1, r2, r3;
                LDSM_X4(r0, r1, r2, r3, bb + 2 * PLANE + bd);
                bh[2 * ntp][0] = r0; bh[2 * ntp][1] = r2;
                bh[2 * ntp + 1][0] = r1; bh[2 * ntp + 1][1] = r3;
                LDSM_X4(r0, r1, r2, r3, bb + 3 * PLANE + bd);
                bl[2 * ntp][0] = r0; bl[2 * ntp][1] = r2;
                bl[2 * ntp + 1][0] = r1; bl[2 * ntp + 1][1] = r3;
            }
#pragma unroll
            for (int mt = 0; mt < 4; ++mt)
#pragma unroll
                for (int nt = 0; nt < 4; ++nt)
                    MMA_BF16(acc[mt][nt], ah[mt], bh[nt]);
#pragma unroll
            for (int mt = 0; mt < 4; ++mt)
#pragma unroll
                for (int nt = 0; nt < 4; ++nt)
                    MMA_BF16(acc[mt][nt], ah[mt], bl[nt]);
#pragma unroll
            for (int mt = 0; mt < 4; ++mt)
#pragma unroll
                for (int nt = 0; nt < 4; ++nt)
                    MMA_BF16(acc[mt][nt], al[mt], bh[nt]);
        }

        if (ch + 2 < nchunk) {
            stage((buf + 2) % 3, (ch + 2) * KC);
            CP_COMMIT();
        }
        buf = (buf + 1) % 3;
    }

    const int er = lane >> 2;
    const int ec = (lane & 3) << 1;
#pragma unroll
    for (int mt = 0; mt < 4; ++mt) {
#pragma unroll
        for (int nt = 0; nt < 4; ++nt) {
            int col = nBase + wn * 32 + nt * 8 + ec;
            float b0 = bias ? bias[col]     : 0.f;
            float b1 = bias ? bias[col + 1] : 0.f;
            int row0 = mBase + wm * 64 + mt * 16 + er;
            float2 v0 = make_float2(acc[mt][nt][0] + b0, acc[mt][nt][1] + b1);
            float2 v1 = make_float2(acc[mt][nt][2] + b0, acc[mt][nt][3] + b1);
            *(float2*)&C[(size_t)row0 * N + col]       = v0;
            *(float2*)&C[(size_t)(row0 + 8) * N + col] = v1;
        }
    }
}

// ---------------------------------------------------------------------------
// GEMM1 fused with RoPE + hi/lo split: x @ Wqkv^T -> q/k/v bf16 planes.
// Epilogue stages the fp32 tile in smem, applies RoPE (q,k) in fp32, splits.
// ---------------------------------------------------------------------------
__global__ void __launch_bounds__(256, 2) gemm_qkv_rope(
    const bf16* __restrict__ Ah_, const bf16* __restrict__ Al_,
    const bf16* __restrict__ Bh_, const bf16* __restrict__ Bl_,
    bf16* __restrict__ qh_, bf16* __restrict__ ql_,
    bf16* __restrict__ kh_, bf16* __restrict__ kl_,
    bf16* __restrict__ vh_, bf16* __restrict__ vl_,
    int M, int N, int K)
{
    extern __shared__ char dsm[];
    const uint32_t sb = smem_u32(dsm);

    const int tid  = threadIdx.x;
    const int wid  = tid >> 5;
    const int lane = tid & 31;
    const int wm   = wid >> 2;
    const int wn   = wid & 3;
    const int mBase = blockIdx.y << 7;
    const int nBase = blockIdx.x << 7;

    const int srow = tid >> 2;
    const int sc   = tid & 3;
    const uint32_t sswz = SWZ(srow * 64 + sc * 16);
    const bf16* gAh = Ah_ + (size_t)(mBase + srow) * K + sc * 8;
    const bf16* gAl = Al_ + (size_t)(mBase + srow) * K + sc * 8;
    const bf16* gBh = Bh_ + (size_t)(nBase + srow) * K + sc * 8;
    const bf16* gBl = Bl_ + (size_t)(nBase + srow) * K + sc * 8;
    const size_t rs64 = (size_t)64 * K;

    const uint32_t aswz = SWZ((wm * 64 + (lane & 15)) * 64 + (lane >> 4) * 16);
    const uint32_t bswz = SWZ((wn * 32 + (lane & 15)) * 64 + (lane >> 4) * 16);

    float acc[4][4][4];
#pragma unroll
    for (int i = 0; i < 4; ++i)
#pragma unroll
        for (int j = 0; j < 4; ++j)
#pragma unroll
            for (int r = 0; r < 4; ++r) acc[i][j][r] = 0.f;

    const int nchunk = K / KC;

    auto stage = [&](int buf, int k0) {
        uint32_t base = sb + (uint32_t)(buf * BUF) + sswz;
        CP_ASYNC16(base,                    gAh + k0);
        CP_ASYNC16(base + 4096,             gAh + k0 + rs64);
        CP_ASYNC16(base + PLANE,            gAl + k0);
        CP_ASYNC16(base + PLANE + 4096,     gAl + k0 + rs64);
        CP_ASYNC16(base + 2 * PLANE,        gBh + k0);
        CP_ASYNC16(base + 2 * PLANE + 4096, gBh + k0 + rs64);
        CP_ASYNC16(base + 3 * PLANE,        gBl + k0);
        CP_ASYNC16(base + 3 * PLANE + 4096, gBl + k0 + rs64);
    };

    stage(0, 0);
    CP_COMMIT();
    if (nchunk > 1) { stage(1, KC); CP_COMMIT(); }

    int buf = 0;
    for (int ch = 0; ch < nchunk; ++ch) {
        if (ch + 1 < nchunk)
            asm volatile("cp.async.wait_group 1;" ::: "memory");
        else
            asm volatile("cp.async.wait_group 0;" ::: "memory");
        __syncthreads();

        const uint32_t bb = sb + (uint32_t)(buf * BUF);

#pragma unroll
        for (int ks = 0; ks < 2; ++ks) {
            const uint32_t kx = (uint32_t)(ks << 5);
            uint32_t ah[4][4], al[4][4], bh[4][2], bl[4][2];
#pragma unroll
            for (int mt = 0; mt < 4; ++mt) {
                uint32_t ad = (aswz ^ kx) + (uint32_t)(mt * 1024);
                LDSM_X4(ah[mt][0], ah[mt][1], ah[mt][2], ah[mt][3], bb + ad);
                LDSM_X4(al[mt][0], al[mt][1], al[mt][2], al[mt][3], bb + PLANE + ad);
            }
#pragma unroll
            for (int ntp = 0; ntp < 2; ++ntp) {
                uint32_t bd = (bswz ^ kx) + (uint32_t)(ntp * 1024);
                uint32_t r0, r1, r2, r3;
                LDSM_X4(r0, r1, r2, r3, bb + 2 * PLANE + bd);
                bh[2 * ntp][0] = r0; bh[2 * ntp][1] = r2;
                bh[2 * ntp + 1][0] = r1; bh[2 * ntp + 1][1] = r3;
                LDSM_X4(r0, r1, r2, r3, bb + 3 * PLANE + bd);
                bl[2 * ntp][0] = r0; bl[2 * ntp][1] = r2;
                bl[2 * ntp + 1][0] = r1; bl[2 * ntp + 1][1] = r3;
            }
#pragma unroll
            for (int mt = 0; mt < 4; ++mt)
#pragma unroll
                for (int nt = 0; nt < 4; ++nt)
                    MMA_BF16(acc[mt][nt], ah[mt], bh[nt]);
#pragma unroll
            for (int mt = 0; mt < 4; ++mt)
#pragma unroll
                for (int nt = 0; nt < 4; ++nt)
                    MMA_BF16(acc[mt][nt], ah[mt], bl[nt]);
#pragma unroll
            for (int mt = 0; mt < 4; ++mt)
#pragma unroll
                for (int nt = 0; nt < 4; ++nt)
                    MMA_BF16(acc[mt][nt], al[mt], bh[nt]);
        }

        if (ch + 2 < nchunk) {
            stage((buf + 2) % 3, (ch + 2) * KC);
            CP_COMMIT();
        }
        buf = (buf + 1) % 3;
    }

    // ---- Fused epilogue: park fp32 tile in smem (stride 132 floats) ----
    __syncthreads();                     // all warps done reading last chunk
    float* st = (float*)dsm;             // 128 x 132 fp32 = 67584 B <= 98304
    const int er = lane >> 2;
    const int ec = (lane & 3) << 1;
#pragma unroll
    for (int mt = 0; mt < 4; ++mt) {
#pragma unroll
        for (int nt = 0; nt < 4; ++nt) {
            int r0 = wm * 64 + mt * 16 + er;
            int c0 = wn * 32 + nt * 8 + ec;
            st[r0 * 132 + c0]           = acc[mt][nt][0];
            st[r0 * 132 + c0 + 1]       = acc[mt][nt][1];
            st[(r0 + 8) * 132 + c0]     = acc[mt][nt][2];
            st[(r0 + 8) * 132 + c0 + 1] = acc[mt][nt][3];
        }
    }
    __syncthreads();

    // ---- RoPE + split: thread owns column pair (hb+i, hb+i+32) ----
    const int pi = tid & 63;             // pair index within tile
    const int hb = (pi >> 5) << 6;       // head base within tile: 0 or 64
    const int i  = pi & 31;
    const int colBase = nBase + hb + i;  // global C3 column
    const int which   = colBase >> 9;    // 0=q, 1=k, 2=v
    const int colMod  = colBase & 511;   // h*64 + i
    bf16 *H, *L;
    if (which == 0)      { H = qh_; L = ql_; }
    else if (which == 1) { H = kh_; L = kl_; }
    else                 { H = vh_; L = vl_; }
    const bool doRope = (which < 2);
    const float inv = (float)exp(-(double)i / 32.0 * 9.210340371976184);

    for (int rr = tid >> 6; rr < 128; rr += 4) {
        const int m = mBase + rr;        // global token index
        float v1 = st[rr * 132 + hb + i];
        float v2 = st[rr * 132 + hb + i + 32];
        float r1 = v1, r2 = v2;
        if (doRope) {
            int t = m & (TSEQ - 1);
            float sn, cs;
            sincosf((float)t * inv, &sn, &cs);
            r1 = v1 * cs - v2 * sn;
            r2 = v2 * cs + v1 * sn;
        }
        size_t o = (size_t)m * DM + colMod;
        H[o]      = bhi(r1);
        L[o]      = blo(r1);
        H[o + 32] = bhi(r2);
        L[o + 32] = blo(r2);
    }
}

// ---------------------------------------------------------------------------
// HMMA banded flash attention (R11/R13-exact: 128 threads, 64-query tile,
// static padded smem, native-V + trans ldmatrix, 4 CTAs/SM)
// ---------------------------------------------------------------------------
#define APAD  72
#define APADB 144

__global__ void __launch_bounds__(128) attn_bf(
    const bf16* __restrict__ qh_, const bf16* __restrict__ ql_,
    const bf16* __restrict__ kh_, const bf16* __restrict__ kl_,
    const bf16* __restrict__ vh_, const bf16* __restrict__ vl_,
    bf16* __restrict__ oh_, bf16* __restrict__ ol_)
{
    __shared__ bf16 Qh[64 * APAD], Ql[64 * APAD];
    __shared__ bf16 Kh[64 * APAD], Kl[64 * APAD];
    __shared__ bf16 Vh[64 * APAD], Vl[64 * APAD];

    const int tid  = threadIdx.x;
    const int wid  = tid >> 5;
    const int lane = tid & 31;
    const int qt = blockIdx.x, h = blockIdx.y, n = blockIdx.z;
    const int q0 = qt * 64;
    const size_t base = (size_t)n * TSEQ * DM + h * HD;

    const uint32_t baseQh = smem_u32(Qh), baseQl = smem_u32(Ql);
    const uint32_t baseKh = smem_u32(Kh), baseKl = smem_u32(Kl);
    const uint32_t baseVh = smem_u32(Vh), baseVl = smem_u32(Vl);

#pragma unroll
    for (int it = 0; it < 4; ++it) {
        int idx = it * 128 + tid;
        int row = idx >> 3;
        int f8  = (idx & 7) << 3;
        size_t g = base + (size_t)(q0 + row) * DM + f8;
        int so = row * APAD + f8;
        *(uint4*)&Qh[so] = *(const uint4*)&qh_[g];
        *(uint4*)&Ql[so] = *(const uint4*)&ql_[g];
    }
    __syncthreads();

    const uint32_t aOff = (uint32_t)((wid * 16 + (lane & 15)) * APADB
                                     + (lane >> 4) * 16);
    uint32_t qh[4][4], ql[4][4];
#pragma unroll
    for (int kt = 0; kt < 4; ++kt) {
        LDSM_X4(qh[kt][0], qh[kt][1], qh[kt][2], qh[kt][3], baseQh + aOff + kt * 32);
        LDSM_X4(ql[kt][0], ql[kt][1], ql[kt][2], ql[kt][3], baseQl + aOff + kt * 32);
    }

    float m_[2] = {-1e30f, -1e30f};
    float l_[2] = {0.f, 0.f};
    float oacc[8][4];
#pragma unroll
    for (int i = 0; i < 8; ++i)
#pragma unroll
        for (int r = 0; r < 4; ++r) oacc[i][r] = 0.f;

    const int kv_begin = max(0, q0 - 128);
    const int kv_end   = min(TSEQ, q0 + 64 + 128);

    const uint32_t bOff = (uint32_t)((lane & 15) * APADB + (lane >> 4) * 16);
    const int rbase = lane >> 2;
    const int cbase = (lane & 3) << 1;

    for (int kc = kv_begin; kc < kv_end; kc += 64) {
        __syncthreads();
#pragma unroll
        for (int it = 0; it < 4; ++it) {
            int idx = it * 128 + tid;
            int row = idx >> 3;
            int f8  = (idx & 7) << 3;
            size_t g = base + (size_t)(kc + row) * DM + f8;
            int so = row * APAD + f8;
            *(uint4*)&Kh[so] = *(const uint4*)&kh_[g];
            *(uint4*)&Kl[so] = *(const uint4*)&kl_[g];
            *(uint4*)&Vh[so] = *(const uint4*)&vh_[g];
            *(uint4*)&Vl[so] = *(const uint4*)&vl_[g];
        }
        __syncthreads();

        float sacc[8][4];
#pragma unroll
        for (int i = 0; i < 8; ++i)
#pragma unroll
            for (int r = 0; r < 4; ++r) sacc[i][r] = 0.f;

#pragma unroll
        for (int ntp = 0; ntp < 4; ++ntp) {
#pragma unroll
            for (int kt = 0; kt < 4; ++kt) {
                uint32_t ad = bOff + (uint32_t)(ntp * 16 * APADB) + (uint32_t)(kt * 32);
                uint32_t r0, r1, r2, r3, s0, s1, s2, s3;
                LDSM_X4(r0, r1, r2, r3, baseKh + ad);
                LDSM_X4(s0, s1, s2, s3, baseKl + ad);
                uint32_t bh0[2] = {r0, r2}, bh1[2] = {r1, r3};
                uint32_t bl0[2] = {s0, s2}, bl1[2] = {s1, s3};
                MMA_BF16(sacc[2 * ntp],     qh[kt], bh0);
                MMA_BF16(sacc[2 * ntp],     qh[kt], bl0);
                MMA_BF16(sacc[2 * ntp],     ql[kt], bh0);
                MMA_BF16(sacc[2 * ntp + 1], qh[kt], bh1);
                MMA_BF16(sacc[2 * ntp + 1], qh[kt], bl1);
                MMA_BF16(sacc[2 * ntp + 1], ql[kt], bh1);
            }
        }

        float mnew[2] = {m_[0], m_[1]};
#pragma unroll
        for (int nt = 0; nt < 8; ++nt) {
            int key0 = kc + nt * 8 + cbase;
#pragma unroll
            for (int half = 0; half < 2; ++half) {
                int q = q0 + wid * 16 + rbase + half * 8;
#pragma unroll
                for (int c = 0; c < 2; ++c) {
                    int diff = key0 + c - q;
                    bool vld = (diff >= -127) && (diff <= 128);
                    float sv = vld ? sacc[nt][half * 2 + c] * ATT_SCALE : -1e30f;
                    sacc[nt][half * 2 + c] = sv;
                    mnew[half] = fmaxf(mnew[half], sv);
                }
            }
        }
#pragma unroll
        for (int off = 1; off <= 2; off <<= 1) {
            mnew[0] = fmaxf(mnew[0], __shfl_xor_sync(0xffffffffu, mnew[0], off));
            mnew[1] = fmaxf(mnew[1], __shfl_xor_sync(0xffffffffu, mnew[1], off));
        }

        float sc0 = __expf(m_[0] - mnew[0]);
        float sc1 = __expf(m_[1] - mnew[1]);
        float ls[2] = {0.f, 0.f};

        uint32_t phi[4][4], plo[4][4];
#pragma unroll
        for (int kt = 0; kt < 4; ++kt) {
            int je = 2 * kt, jo = 2 * kt + 1;
            float p0 = __expf(sacc[je][0] - mnew[0]);
            float p1 = __expf(sacc[je][1] - mnew[0]);
            float p2 = __expf(sacc[je][2] - mnew[1]);
            float p3 = __expf(sacc[je][3] - mnew[1]);
            float p4 = __expf(sacc[jo][0] - mnew[0]);
            float p5 = __expf(sacc[jo][1] - mnew[0]);
            float p6 = __expf(sacc[jo][2] - mnew[1]);
            float p7 = __expf(sacc[jo][3] - mnew[1]);
            ls[0] += p0 + p1 + p4 + p5;
            ls[1] += p2 + p3 + p6 + p7;
            phi[kt][0] = pack_hi(p0, p1); plo[kt][0] = pack_lo(p0, p1);
            phi[kt][1] = pack_hi(p2, p3); plo[kt][1] = pack_lo(p2, p3);
            phi[kt][2] = pack_hi(p4, p5); plo[kt][2] = pack_lo(p4, p5);
            phi[kt][3] = pack_hi(p6, p7); plo[kt][3] = pack_lo(p6, p7);
        }
#pragma unroll
        for (int off = 1; off <= 2; off <<= 1) {
            ls[0] += __shfl_xor_sync(0xffffffffu, ls[0], off);
            ls[1] += __shfl_xor_sync(0xffffffffu, ls[1], off);
        }
        l_[0] = l_[0] * sc0 + ls[0];
        l_[1] = l_[1] * sc1 + ls[1];
        m_[0] = mnew[0];
        m_[1] = mnew[1];

#pragma unroll
        for (int nt = 0; nt < 8; ++nt) {
            oacc[nt][0] *= sc0; oacc[nt][1] *= sc0;
            oacc[nt][2] *= sc1; oacc[nt][3] *= sc1;
        }

#pragma unroll
        for (int ntp = 0; ntp < 4; ++ntp) {
#pragma unroll
            for (int kt = 0; kt < 4; ++kt) {
                uint32_t ad = bOff + (uint32_t)(kt * 16 * APADB) + (uint32_t)(ntp * 32);
                uint32_t r0, r1, r2, r3, s0, s1, s2, s3;
                LDSM_X4_T(r0, r1, r2, r3, baseVh + ad);
                LDSM_X4_T(s0, s1, s2, s3, baseVl + ad);
                uint32_t bh0[2] = {r0, r1}, bh1[2] = {r2, r3};
                uint32_t bl0[2] = {s0, s1}, bl1[2] = {s2, s3};
                MMA_BF16(oacc[2 * ntp],     phi[kt], bh0);
                MMA_BF16(oacc[2 * ntp],     phi[kt], bl0);
                MMA_BF16(oacc[2 * ntp],     plo[kt], bh0);
                MMA_BF16(oacc[2 * ntp + 1], phi[kt], bh1);
                MMA_BF16(oacc[2 * ntp + 1], phi[kt], bl1);
                MMA_BF16(oacc[2 * ntp + 1], plo[kt], bh1);
            }
        }
    }

    float inv0 = 1.f / l_[0];
    float inv1 = 1.f / l_[1];
    int q = q0 + wid * 16 + rbase;
#pragma unroll
    for (int nt = 0; nt < 8; ++nt) {
        int d = nt * 8 + cbase;
        size_t o0 = base + (size_t)q * DM + d;
        size_t o1 = base + (size_t)(q + 8) * DM + d;
        float a0 = oacc[nt][0] * inv0, a1 = oacc[nt][1] * inv0;
        float a2 = oacc[nt][2] * inv1, a3 = oacc[nt][3] * inv1;
        *(uint32_t*)&oh_[o0] = pack_hi(a0, a1);
        *(uint32_t*)&ol_[o0] = pack_lo(a0, a1);
        *(uint32_t*)&oh_[o1] = pack_hi(a2, a3);
        *(uint32_t*)&ol_[o1] = pack_lo(a2, a3);
    }
}

// ---------------------------------------------------------------------------
extern "C" void kernel_launch(void* const* d_in, const int* in_sizes, int n_in,
                              void* d_out, int out_size)
{
    const float* x    = (const float*)d_in[0];
    const float* wqkv = (const float*)d_in[1];
    const float* outw = (const float*)d_in[2];
    const float* outb = (const float*)d_in[3];
    float* out = (float*)d_out;

    void *xh, *xl, *wqh, *wql, *owh, *owl;
    void *qhp, *qlp, *khp, *klp, *vhp, *vlp, *ahp, *alp;
    cudaGetSymbolAddress(&xh, g_xh);   cudaGetSymbolAddress(&xl, g_xl);
    cudaGetSymbolAddress(&wqh, g_wqh); cudaGetSymbolAddress(&wql, g_wql);
    cudaGetSymbolAddress(&owh, g_owh); cudaGetSymbolAddress(&owl, g_owl);
    cudaGetSymbolAddress(&qhp, g_qh);  cudaGetSymbolAddress(&qlp, g_ql);
    cudaGetSymbolAddress(&khp, g_kh);  cudaGetSymbolAddress(&klp, g_kl);
    cudaGetSymbolAddress(&vhp, g_vh);  cudaGetSymbolAddress(&vlp, g_vl);
    cudaGetSymbolAddress(&ahp, g_ah);  cudaGetSymbolAddress(&alp, g_al);

    cudaFuncSetAttribute(gemm_bf,
                         cudaFuncAttributeMaxDynamicSharedMemorySize, GEMM_SMEM);
    cudaFuncSetAttribute(gemm_qkv_rope,
                         cudaFuncAttributeMaxDynamicSharedMemorySize, GEMM_SMEM);

    split_f4<<<(NTOK * DM / 4 + 255) / 256, 256>>>(x, (bf16*)xh, (bf16*)xl,
                                                   NTOK * DM / 4);
    split_f4<<<(C3 * DM / 4 + 255) / 256, 256>>>(wqkv, (bf16*)wqh, (bf16*)wql,
                                                 C3 * DM / 4);
    split_f4<<<(DM * DM / 4 + 255) / 256, 256>>>(outw, (bf16*)owh, (bf16*)owl,
                                                 DM * DM / 4);

    // 1) QKV projection fused with RoPE + split -> q/k/v planes
    dim3 g1(C3 / 128, NTOK / 128);
    gemm_qkv_rope<<<g1, 256, GEMM_SMEM>>>(
        (bf16*)xh, (bf16*)xl, (bf16*)wqh, (bf16*)wql,
        (bf16*)qhp, (bf16*)qlp, (bf16*)khp, (bf16*)klp, (bf16*)vhp, (bf16*)vlp,
        NTOK, C3, DM);

    // 2) Banded attention
    dim3 g3(TSEQ / 64, NH, NB);
    attn_bf<<<g3, 128>>>((bf16*)qhp, (bf16*)qlp, (bf16*)khp, (bf16*)klp,
                         (bf16*)vhp, (bf16*)vlp, (bf16*)ahp, (bf16*)alp);

    // 3) Output projection + bias
    dim3 g4(DM / 128, NTOK / 128);
    gemm_bf<<<g4, 256, GEMM_SMEM>>>((bf16*)ahp, (bf16*)alp, (bf16*)owh, (bf16*)owl,
                                    out, outb, NTOK, DM, DM);
}